// round 14
// baseline (speedup 1.0000x reference)
#include <cuda_runtime.h>
#include <math.h>
#include <stdint.h>

#define B_N 4096
#define D_N 16384

// W_FIRST = 2 - 10 * (2/49), W_LAST = 2 - W_FIRST, batch_step = (W_FIRST-W_LAST)/(B-1)
#define EPOCH_STEP (2.0 / 49.0)
#define W_FIRST_D  (2.0 - 10.0 * EPOCH_STEP)   /* ~1.5918367346938775 */
#define W_LAST_D   (2.0 - W_FIRST_D)
#define BATCH_STEP_D ((W_FIRST_D - W_LAST_D) / (double)(B_N - 1))

// Sortable u32 keys: raw IEEE bits of difficulty (always > 0, so bit pattern
// is order-preserving). Ties (prob ~B^2*2^-32) perturb the result ~1.7e-7
// relative, 4 orders under the 1e-3 threshold -> strict '<' count suffices.
__device__ __align__(16) unsigned int g_keys[B_N];

// Dynamic row queue for K1. Invariant: == 0 at every kernel_launch entry.
// K1 consumes it; K2 (which always runs after K1) resets it to 0.
__device__ unsigned int g_row_ctr = 0;

#define K1_BLOCKS 592   // 148 SMs * 4 blocks = 32 warps/SM, single resident wave

// ---------------------------------------------------------------------------
// Kernel 1: difficulty[i] = 0.5*loss[i] + 0.5*||gradients[i,:]||_2
// Warp-per-row with dynamic atomic work queue: no __syncthreads, no smem,
// single resident wave, perfect 1-row-granularity load balance.
// Each lane covers 128 float4 (32 lanes * 128 * 4 floats = 16384 = D). 16
// outer iterations x 8 independent streaming LDG.128, 4 accumulators.
// ---------------------------------------------------------------------------
__global__ __launch_bounds__(256) void difficulty_kernel(
    const float* __restrict__ loss,
    const float4* __restrict__ grad,       // [B, D/4]
    float* __restrict__ out)               // out[0]=acc, out[1..B]=difficulty
{
    const int tid  = threadIdx.x;
    const int lane = tid & 31;

    if (blockIdx.x == 0 && tid == 0) out[0] = 0.0f;   // reset accumulator

    for (;;) {
        // Lane 0 grabs the next row; broadcast to the warp.
        unsigned int row;
        if (lane == 0) row = atomicAdd(&g_row_ctr, 1u);
        row = __shfl_sync(0xFFFFFFFFu, row, 0);
        if (row >= B_N) break;

        const float4* __restrict__ g = grad + (size_t)row * (D_N / 4);

        float s0 = 0.0f, s1 = 0.0f, s2 = 0.0f, s3 = 0.0f;
#pragma unroll 4
        for (int it = 0; it < 16; it++) {        // 16 * 8 = 128 float4 per lane
            float4 a = __ldcs(&g[lane + (it * 8 + 0) * 32]);
            float4 b = __ldcs(&g[lane + (it * 8 + 1) * 32]);
            float4 c = __ldcs(&g[lane + (it * 8 + 2) * 32]);
            float4 d = __ldcs(&g[lane + (it * 8 + 3) * 32]);
            float4 e = __ldcs(&g[lane + (it * 8 + 4) * 32]);
            float4 f = __ldcs(&g[lane + (it * 8 + 5) * 32]);
            float4 h = __ldcs(&g[lane + (it * 8 + 6) * 32]);
            float4 q = __ldcs(&g[lane + (it * 8 + 7) * 32]);
            s0 = fmaf(a.x, a.x, s0); s0 = fmaf(a.y, a.y, s0);
            s0 = fmaf(a.z, a.z, s0); s0 = fmaf(a.w, a.w, s0);
            s1 = fmaf(b.x, b.x, s1); s1 = fmaf(b.y, b.y, s1);
            s1 = fmaf(b.z, b.z, s1); s1 = fmaf(b.w, b.w, s1);
            s2 = fmaf(c.x, c.x, s2); s2 = fmaf(c.y, c.y, s2);
            s2 = fmaf(c.z, c.z, s2); s2 = fmaf(c.w, c.w, s2);
            s3 = fmaf(d.x, d.x, s3); s3 = fmaf(d.y, d.y, s3);
            s3 = fmaf(d.z, d.z, s3); s3 = fmaf(d.w, d.w, s3);
            s0 = fmaf(e.x, e.x, s0); s0 = fmaf(e.y, e.y, s0);
            s0 = fmaf(e.z, e.z, s0); s0 = fmaf(e.w, e.w, s0);
            s1 = fmaf(f.x, f.x, s1); s1 = fmaf(f.y, f.y, s1);
            s1 = fmaf(f.z, f.z, s1); s1 = fmaf(f.w, f.w, s1);
            s2 = fmaf(h.x, h.x, s2); s2 = fmaf(h.y, h.y, s2);
            s2 = fmaf(h.z, h.z, s2); s2 = fmaf(h.w, h.w, s2);
            s3 = fmaf(q.x, q.x, s3); s3 = fmaf(q.y, q.y, s3);
            s3 = fmaf(q.z, q.z, s3); s3 = fmaf(q.w, q.w, s3);
        }
        float s = (s0 + s1) + (s2 + s3);

        // warp reduce
#pragma unroll
        for (int off = 16; off > 0; off >>= 1)
            s += __shfl_xor_sync(0xFFFFFFFFu, s, off);

        if (lane == 0) {
            float d = 0.5f * __ldg(&loss[row]) + 0.5f * sqrtf(s);
            out[1 + row] = d;
            g_keys[row] = __float_as_uint(d);
        }
    }

    // PDL: allow the dependent rank kernel to launch; its griddepsync still
    // guarantees visibility of all writes above (they precede this trigger).
    cudaTriggerProgrammaticLaunchCompletion();
}

// ---------------------------------------------------------------------------
// Kernel 2: counting rank + weighted loss accumulation (u32 keys, PDL).
// Each block owns 4 consecutive i's; 256 threads scan all B keys as uint4;
// REDUX warp reduction. One atomicAdd per block. Block 0 resets the row queue
// for the next graph replay.
// ---------------------------------------------------------------------------
#define IPB 4          // i's per block
#define K2_THREADS 256

__global__ __launch_bounds__(K2_THREADS) void rank_weight_kernel(
    const float* __restrict__ loss,
    float* __restrict__ out)
{
    const int i0  = blockIdx.x * IPB;
    const int tid = threadIdx.x;

    // Prologue independent of K1's output, runs under K1's tail.
    float l0 = (tid == 0) ? __ldg(&loss[i0 + 0]) : 0.0f;
    float l1 = (tid == 0) ? __ldg(&loss[i0 + 1]) : 0.0f;
    float l2 = (tid == 0) ? __ldg(&loss[i0 + 2]) : 0.0f;
    float l3 = (tid == 0) ? __ldg(&loss[i0 + 3]) : 0.0f;

    // Wait for K1 grid completion (makes g_keys globally visible).
    cudaGridDependencySynchronize();

    // Reset the K1 row queue for the next replay (after K1 is fully done).
    if (blockIdx.x == 0 && tid == 0) g_row_ctr = 0;

    unsigned int ki[IPB];
#pragma unroll
    for (int k = 0; k < IPB; k++) ki[k] = g_keys[i0 + k];

    int cnt[IPB] = {0, 0, 0, 0};

    const uint4* __restrict__ keys4 = (const uint4*)g_keys;  // 4 keys per uint4

#pragma unroll 4
    for (int p = tid; p < B_N / 4; p += K2_THREADS) {
        uint4 v = keys4[p];
#pragma unroll
        for (int k = 0; k < IPB; k++) {
            cnt[k] += (v.x < ki[k]);
            cnt[k] += (v.y < ki[k]);
            cnt[k] += (v.z < ki[k]);
            cnt[k] += (v.w < ki[k]);
        }
    }

    // REDUX warp reduction (single instruction per counter)
#pragma unroll
    for (int k = 0; k < IPB; k++)
        cnt[k] = __reduce_add_sync(0xFFFFFFFFu, cnt[k]);

    __shared__ int warp_cnt[K2_THREADS / 32][IPB];
    if ((tid & 31) == 0) {
#pragma unroll
        for (int k = 0; k < IPB; k++)
            warp_cnt[tid >> 5][k] = cnt[k];
    }
    __syncthreads();

    if (tid == 0) {
        int rank0 = 0, rank1 = 0, rank2 = 0, rank3 = 0;
#pragma unroll
        for (int w = 0; w < K2_THREADS / 32; w++) {
            rank0 += warp_cnt[w][0];
            rank1 += warp_cnt[w][1];
            rank2 += warp_cnt[w][2];
            rank3 += warp_cnt[w][3];
        }
        float contrib =
            l0 * (float)(W_FIRST_D - BATCH_STEP_D * (double)rank0) +
            l1 * (float)(W_FIRST_D - BATCH_STEP_D * (double)rank1) +
            l2 * (float)(W_FIRST_D - BATCH_STEP_D * (double)rank2) +
            l3 * (float)(W_FIRST_D - BATCH_STEP_D * (double)rank3);
        atomicAdd(&out[0], contrib * (1.0f / (float)B_N));
    }
}

// ---------------------------------------------------------------------------
extern "C" void kernel_launch(void* const* d_in, const int* in_sizes, int n_in,
                              void* d_out, int out_size)
{
    const float*  loss = (const float*)d_in[0];
    const float4* grad = (const float4*)d_in[1];
    float* out = (float*)d_out;

    difficulty_kernel<<<K1_BLOCKS, 256>>>(loss, grad, out);

    // PDL launch for K2: overlaps its ramp with K1's tail.
    cudaLaunchConfig_t cfg = {};
    cfg.gridDim  = dim3(B_N / IPB);
    cfg.blockDim = dim3(K2_THREADS);
    cfg.dynamicSmemBytes = 0;
    cfg.stream = 0;
    cudaLaunchAttribute attr[1];
    attr[0].id = cudaLaunchAttributeProgrammaticStreamSerialization;
    attr[0].val.programmaticStreamSerializationAllowed = 1;
    cfg.attrs = attr;
    cfg.numAttrs = 1;
    cudaLaunchKernelEx(&cfg, rank_weight_kernel, loss, out);
}

// round 15
// speedup vs baseline: 1.0464x; 1.0464x over previous
#include <cuda_runtime.h>
#include <math.h>
#include <stdint.h>

#define B_N 4096
#define D_N 16384

// W_FIRST = 2 - 10 * (2/49), W_LAST = 2 - W_FIRST, batch_step = (W_FIRST-W_LAST)/(B-1)
#define EPOCH_STEP (2.0 / 49.0)
#define W_FIRST_D  (2.0 - 10.0 * EPOCH_STEP)   /* ~1.5918367346938775 */
#define W_LAST_D   (2.0 - W_FIRST_D)
#define BATCH_STEP_D ((W_FIRST_D - W_LAST_D) / (double)(B_N - 1))

// Sortable u32 keys: raw IEEE bits of difficulty (always > 0 -> bit pattern
// order-preserving). Tie probability ~B^2*2^-32 perturbs result ~1.7e-7 rel.
__device__ __align__(16) unsigned int g_keys[B_N];

// Grid gate counters. Invariant: both == 0 at every kernel_launch entry;
// the last rank-phase completer resets them for the next graph replay.
__device__ unsigned int g_done  = 0;
__device__ unsigned int g_done2 = 0;

#define N_K2 1024          // blocks that carry rank work (last 1024 finishers)
#define IPB  4             // i's per rank block
#define THREADS 128

// ---------------------------------------------------------------------------
// Fused kernel.
// Phase 1 (all 4096 blocks, block-per-row): difficulty + sortable key.
// Gate: threadfence + atomicAdd(g_done). First 3072 finishers exit (freeing
// SM slots); last 1024 spin until all rows done, then run the rank phase
// in-place with zero launch/ramp cost.
// Deadlock-free: >=10 resident blocks/SM (launch_bounds) = 1480 slots > 1024
// spinners, so straggler blocks always have free slots to run phase 1.
// ---------------------------------------------------------------------------
__global__ __launch_bounds__(THREADS, 10) void fused_kernel(
    const float* __restrict__ loss,
    const float4* __restrict__ grad,       // [B, D/4]
    float* __restrict__ out)               // out[0]=weighted_loss, out[1..B]=difficulty
{
    const int row = blockIdx.x;
    const int tid = threadIdx.x;

    if (row == 0 && tid == 0) out[0] = 0.0f;   // reset accumulator (graph replay safe)

    // ---- Phase 1: row sum of squares (32 float4 per thread, 4 accumulators)
    const float4* __restrict__ g = grad + (size_t)row * (D_N / 4);

    float s0 = 0.0f, s1 = 0.0f, s2 = 0.0f, s3 = 0.0f;
#pragma unroll
    for (int it = 0; it < 8; it++) {
        float4 a = __ldcs(&g[tid + (it * 4 + 0) * THREADS]);
        float4 b = __ldcs(&g[tid + (it * 4 + 1) * THREADS]);
        float4 c = __ldcs(&g[tid + (it * 4 + 2) * THREADS]);
        float4 d = __ldcs(&g[tid + (it * 4 + 3) * THREADS]);
        s0 = fmaf(a.x, a.x, s0); s0 = fmaf(a.y, a.y, s0);
        s0 = fmaf(a.z, a.z, s0); s0 = fmaf(a.w, a.w, s0);
        s1 = fmaf(b.x, b.x, s1); s1 = fmaf(b.y, b.y, s1);
        s1 = fmaf(b.z, b.z, s1); s1 = fmaf(b.w, b.w, s1);
        s2 = fmaf(c.x, c.x, s2); s2 = fmaf(c.y, c.y, s2);
        s2 = fmaf(c.z, c.z, s2); s2 = fmaf(c.w, c.w, s2);
        s3 = fmaf(d.x, d.x, s3); s3 = fmaf(d.y, d.y, s3);
        s3 = fmaf(d.z, d.z, s3); s3 = fmaf(d.w, d.w, s3);
    }
    float s = (s0 + s1) + (s2 + s3);

    // warp reduce
#pragma unroll
    for (int off = 16; off > 0; off >>= 1)
        s += __shfl_xor_sync(0xFFFFFFFFu, s, off);

    __shared__ float warp_sums[THREADS / 32];
    __shared__ unsigned int s_old;
    if ((tid & 31) == 0) warp_sums[tid >> 5] = s;
    __syncthreads();

    if (tid == 0) {
        float tot = warp_sums[0] + warp_sums[1] + warp_sums[2] + warp_sums[3];
        float d = 0.5f * __ldg(&loss[row]) + 0.5f * sqrtf(tot);
        out[1 + row] = d;
        g_keys[row] = __float_as_uint(d);
        // Publish this row, get completion order.
        __threadfence();
        s_old = atomicAdd(&g_done, 1u);
    }
    __syncthreads();
    const unsigned int old = s_old;

    // ---- First 3072 finishers exit, freeing SM slots for stragglers.
    if (old < (unsigned)(B_N - N_K2)) return;

    // ---- Gate: wait until all rows are published.
    if (tid == 0) {
        if (*(volatile unsigned int*)&g_done < (unsigned)B_N) {
            do { __nanosleep(128); }
            while (*(volatile unsigned int*)&g_done < (unsigned)B_N);
        }
    }
    __syncthreads();
    __threadfence();   // acquire: make all g_keys/out writes visible

    // ---- Phase 2: counting rank + weighted loss (proven R8 body).
    const int k2 = (int)(old - (unsigned)(B_N - N_K2));   // 0..N_K2-1
    const int i0 = k2 * IPB;

    unsigned int ki[IPB];
#pragma unroll
    for (int k = 0; k < IPB; k++) ki[k] = g_keys[i0 + k];

    int cnt[IPB] = {0, 0, 0, 0};

    const uint4* __restrict__ keys4 = (const uint4*)g_keys;  // 4 keys per uint4

#pragma unroll 4
    for (int p = tid; p < B_N / 4; p += THREADS) {
        uint4 v = keys4[p];
#pragma unroll
        for (int k = 0; k < IPB; k++) {
            cnt[k] += (v.x < ki[k]);
            cnt[k] += (v.y < ki[k]);
            cnt[k] += (v.z < ki[k]);
            cnt[k] += (v.w < ki[k]);
        }
    }

    // REDUX warp reduction
#pragma unroll
    for (int k = 0; k < IPB; k++)
        cnt[k] = __reduce_add_sync(0xFFFFFFFFu, cnt[k]);

    __shared__ int warp_cnt[THREADS / 32][IPB];
    if ((tid & 31) == 0) {
#pragma unroll
        for (int k = 0; k < IPB; k++)
            warp_cnt[tid >> 5][k] = cnt[k];
    }
    __syncthreads();

    if (tid == 0) {
        float contrib = 0.0f;
#pragma unroll
        for (int k = 0; k < IPB; k++) {
            int rank = warp_cnt[0][k] + warp_cnt[1][k] + warp_cnt[2][k] + warp_cnt[3][k];
            float w = (float)(W_FIRST_D - BATCH_STEP_D * (double)rank);
            contrib += __ldg(&loss[i0 + k]) * w;
        }
        atomicAdd(&out[0], contrib * (1.0f / (float)B_N));

        // Replay-safe counter reset: the last rank-block to finish resets.
        // All spinners are provably past the gate by then.
        unsigned int d2 = atomicAdd(&g_done2, 1u);
        if (d2 == (unsigned)(N_K2 - 1)) {
            g_done  = 0u;
            g_done2 = 0u;
        }
    }
}

// ---------------------------------------------------------------------------
extern "C" void kernel_launch(void* const* d_in, const int* in_sizes, int n_in,
                              void* d_out, int out_size)
{
    const float*  loss = (const float*)d_in[0];
    const float4* grad = (const float4*)d_in[1];
    float* out = (float*)d_out;

    fused_kernel<<<B_N, THREADS>>>(loss, grad, out);
}